// round 8
// baseline (speedup 1.0000x reference)
#include <cuda_runtime.h>
#include <cuda_fp16.h>
#include <math.h>
#include <stdint.h>

#define Bn   128
#define Cc   256
#define Np   4096
#define CQ   64
#define BN_EPS 1e-5f
#define NT   128                 // n-tile per CTA
#define NTILES (Np / NT)         // 32

// ---------------- scratch (no allocations allowed) ----------------
__device__ float g_tk[Bn * CQ];
__device__ float g_energy[Bn * Np];
__device__ float g_yp[Bn * NTILES * Cc];
__device__ float g_zp[Bn * NTILES];
__device__ float g_d[Bn * Cc];

// ---------------- helpers ----------------
__device__ __forceinline__ uint32_t smem_u32(const void* p) {
    uint32_t a;
    asm("{ .reg .u64 t; cvta.to.shared.u64 t, %1; cvt.u32.u64 %0, t; }" : "=r"(a) : "l"(p));
    return a;
}
__device__ __forceinline__ void ldsm4(uint32_t (&r)[4], uint32_t addr) {
    asm volatile("ldmatrix.sync.aligned.m8n8.x4.shared.b16 {%0,%1,%2,%3}, [%4];"
                 : "=r"(r[0]), "=r"(r[1]), "=r"(r[2]), "=r"(r[3]) : "r"(addr));
}
__device__ __forceinline__ void ldsm2t(uint32_t (&r)[2], uint32_t addr) {
    asm volatile("ldmatrix.sync.aligned.m8n8.x2.trans.shared.b16 {%0,%1}, [%2];"
                 : "=r"(r[0]), "=r"(r[1]) : "r"(addr));
}
__device__ __forceinline__ void mma16816(float (&c)[4], const uint32_t (&a)[4],
                                         uint32_t b0, uint32_t b1) {
    asm volatile(
        "mma.sync.aligned.m16n8k16.row.col.f32.f16.f16.f32 "
        "{%0,%1,%2,%3}, {%4,%5,%6,%7}, {%8,%9}, {%0,%1,%2,%3};"
        : "+f"(c[0]), "+f"(c[1]), "+f"(c[2]), "+f"(c[3])
        : "r"(a[0]), "r"(a[1]), "r"(a[2]), "r"(a[3]), "r"(b0), "r"(b1));
}
__device__ __forceinline__ uint32_t h2bits(half2 h) {
    return *(uint32_t*)&h;
}
__device__ __forceinline__ void cvt4h(float4 v, uint32_t& h01, uint32_t& h23) {
    h01 = h2bits(__floats2half2_rn(v.x, v.y));
    h23 = h2bits(__floats2half2_rn(v.z, v.w));
}
__device__ __forceinline__ void split4h(float4 v, uint32_t& h01, uint32_t& h23,
                                        uint32_t& l01, uint32_t& l23) {
    half2 p0 = __floats2half2_rn(v.x, v.y);
    half2 p1 = __floats2half2_rn(v.z, v.w);
    float2 f0 = __half22float2(p0);
    float2 f1 = __half22float2(p1);
    half2 q0 = __floats2half2_rn(v.x - f0.x, v.y - f0.y);
    half2 q1 = __floats2half2_rn(v.z - f1.x, v.w - f1.y);
    h01 = h2bits(p0); h23 = h2bits(p1);
    l01 = h2bits(q0); l23 = h2bits(q1);
}

// smem layout (bytes)
#define WSTRB     528            // wq row stride (264 halves)
#define XSTRB     272            // x row stride (136 halves)
#define OFF_WQH   0              // 64*528  = 33792
#define OFF_XH    33792          // 256*272 = 69632
#define OFF_XL    103424         // 69632
#define OFF_E     173056         // 128 floats
#define OFF_W     173568         // 128 floats
#define OFF_TK    174080         // 64 floats
#define OFF_BQ    174336         // 64 floats
#define OFF_ZR    174592         // 4 floats
#define ESMEM     174656

// ---------------- kernel 0: tk = tanh(wk @ x_key + bk) ----------------
__global__ void tk_kernel(const float* __restrict__ xk,
                          const float* __restrict__ wk,
                          const float* __restrict__ bk,
                          float* __restrict__ tk) {
    __shared__ float xs[Cc];
    int b = blockIdx.x;
    for (int i = threadIdx.x; i < Cc; i += blockDim.x) xs[i] = xk[b * Cc + i];
    __syncthreads();
    int o = threadIdx.x;
    if (o < CQ) {
        float s = bk[o];
        const float* wr = wk + o * Cc;
        #pragma unroll 8
        for (int c = 0; c < Cc; ++c) s += wr[c] * xs[c];
        tk[b * CQ + o] = tanhf(s);
    }
}

// ---------------- fused kernel: energy + exp + y partials ----------------
// grid (32, 128): CTA = (b, 128-n tile). 512 threads = 16 warps x 8 n.
__global__ void __launch_bounds__(512)
fused_kernel(const float* __restrict__ x,
             const float* __restrict__ wq,
             const float* __restrict__ bq,
             const float* __restrict__ tk,
             float* __restrict__ energy,
             float* __restrict__ yp,
             float* __restrict__ zp) {
    extern __shared__ char sm[];
    const uint32_t sb = smem_u32(sm);
    const int tid  = threadIdx.x;
    const int warp = tid >> 5;
    const int lane = tid & 31;
    const int b    = blockIdx.y;
    const int tile = blockIdx.x;
    const int n0   = tile * NT;

    float* tk_s = (float*)(sm + OFF_TK);
    float* bq_s = (float*)(sm + OFF_BQ);
    float* e_s  = (float*)(sm + OFF_E);
    float* w_s  = (float*)(sm + OFF_W);
    float* zr_s = (float*)(sm + OFF_ZR);
    if (tid < CQ) {
        tk_s[tid] = tk[b * CQ + tid];
        bq_s[tid] = bq[tid];
    }

    // ---- stage wq (fp16 hi only) ----
    {
        const float4* wq4 = (const float4*)wq;
        #pragma unroll
        for (int f = 0; f < 8; ++f) {
            int idx = f * 512 + tid;       // 4096 float4 = 64 o x 64 j (c=4j)
            int o = idx >> 6;
            int j = idx & 63;
            float4 v = wq4[idx];
            uint32_t h01, h23;
            cvt4h(v, h01, h23);
            *(uint2*)(sm + OFF_WQH + (uint32_t)o * WSTRB + j * 8) = make_uint2(h01, h23);
        }
    }

    // accumulators: 4 m-tiles (o) x 4 (single 8-n tile)
    float acc[4][4];
    #pragma unroll
    for (int mt = 0; mt < 4; ++mt)
        #pragma unroll
        for (int e = 0; e < 4; ++e) acc[mt][e] = 0.f;

    const uint32_t a_off = (uint32_t)(lane & 15) * WSTRB + (uint32_t)(lane >> 4) * 16;
    const uint32_t b_off = (uint32_t)(((lane >> 3) & 1) * 8 + (lane & 7)) * XSTRB
                         + (uint32_t)warp * 16;

    const float* xg = x + ((size_t)b * Cc) * Np + n0;

    // staging coords: chunk = 32 c x 32 float4 = 1024 float4, 2 per thread
    int sc[2], sj[2];
    #pragma unroll
    for (int f = 0; f < 2; ++f) {
        int idx = f * 512 + tid;
        sc[f] = idx >> 5;
        sj[f] = idx & 31;
    }

    float4 pre[2];
    #pragma unroll
    for (int f = 0; f < 2; ++f)
        pre[f] = *(const float4*)(xg + (size_t)sc[f] * Np + 4 * sj[f]);

    for (int ch = 0; ch < 8; ++ch) {
        // convert + store chunk ch (hi/lo split of x)
        #pragma unroll
        for (int f = 0; f < 2; ++f) {
            uint32_t h01, h23, l01, l23;
            split4h(pre[f], h01, h23, l01, l23);
            uint32_t off = (uint32_t)(ch * 32 + sc[f]) * XSTRB + sj[f] * 8;
            *(uint2*)(sm + OFF_XH + off) = make_uint2(h01, h23);
            *(uint2*)(sm + OFF_XL + off) = make_uint2(l01, l23);
        }
        __syncthreads();

        // prefetch next chunk (hides under MMAs)
        if (ch < 7) {
            #pragma unroll
            for (int f = 0; f < 2; ++f)
                pre[f] = *(const float4*)(xg + (size_t)((ch + 1) * 32 + sc[f]) * Np + 4 * sj[f]);
        }

        #pragma unroll
        for (int kk = 0; kk < 2; ++kk) {
            uint32_t c_b  = (uint32_t)(ch * 32 + kk * 16) * 2;
            uint32_t krow = (uint32_t)(ch * 32 + kk * 16) * XSTRB;

            uint32_t a_h[4][4];
            #pragma unroll
            for (int mt = 0; mt < 4; ++mt)
                ldsm4(a_h[mt], sb + OFF_WQH + (uint32_t)mt * (16 * WSTRB) + c_b + a_off);
            uint32_t b_hi[2], b_lo[2];
            ldsm2t(b_hi, sb + OFF_XH + krow + b_off);
            ldsm2t(b_lo, sb + OFF_XL + krow + b_off);

            #pragma unroll
            for (int mt = 0; mt < 4; ++mt) {
                mma16816(acc[mt], a_h[mt], b_hi[0], b_hi[1]);
                mma16816(acc[mt], a_h[mt], b_lo[0], b_lo[1]);
            }
        }
    }

    // ---- energy epilogue (warp owns 8 n, all 64 o) ----
    {
        const int r = lane >> 2;
        float s0 = 0.f, s1 = 0.f;
        #pragma unroll
        for (int mt = 0; mt < 4; ++mt) {
            float bq1 = bq_s[mt * 16 + r],     tk1 = tk_s[mt * 16 + r];
            float bq2 = bq_s[mt * 16 + r + 8], tk2 = tk_s[mt * 16 + r + 8];
            s0 += tanhf(acc[mt][0] + bq1) * tk1 + tanhf(acc[mt][2] + bq2) * tk2;
            s1 += tanhf(acc[mt][1] + bq1) * tk1 + tanhf(acc[mt][3] + bq2) * tk2;
        }
        #pragma unroll
        for (int d = 4; d < 32; d <<= 1) {
            s0 += __shfl_xor_sync(0xFFFFFFFFu, s0, d);
            s1 += __shfl_xor_sync(0xFFFFFFFFu, s1, d);
        }
        if (lane < 4) {
            int nl = warp * 8 + 2 * lane;
            float2 ev = make_float2(s0, s1);
            *(float2*)(e_s + nl) = ev;
            *(float2*)(energy + (size_t)b * Np + n0 + nl) = ev;
        }
    }
    __syncthreads();

    // ---- w = exp(e) (|e| < 64, no overflow) + Z partial ----
    if (tid < NT) {
        float w = expf(e_s[tid]);
        w_s[tid] = w;
        float s = w;
        #pragma unroll
        for (int d = 16; d; d >>= 1) s += __shfl_xor_sync(0xFFFFFFFFu, s, d);
        if (lane == 0) zr_s[tid >> 5] = s;
    }
    __syncthreads();
    if (tid == 0) zp[b * NTILES + tile] = zr_s[0] + zr_s[1] + zr_s[2] + zr_s[3];

    // ---- y partial: y_p[c] = sum_n x[c,n] * w[n]  (x = hi + lo from smem) ----
    if (tid < Cc) {
        int c = tid;
        const uint2* hrow = (const uint2*)(sm + OFF_XH + (uint32_t)c * XSTRB);
        const uint2* lrow = (const uint2*)(sm + OFF_XL + (uint32_t)c * XSTRB);
        float accy = 0.f;
        #pragma unroll 8
        for (int j = 0; j < 32; ++j) {
            uint2 h = hrow[j];
            uint2 l = lrow[j];
            float4 w4 = *(const float4*)(w_s + 4 * j);
            float2 h0 = __half22float2(*(half2*)&h.x);
            float2 h1 = __half22float2(*(half2*)&h.y);
            float2 l0 = __half22float2(*(half2*)&l.x);
            float2 l1 = __half22float2(*(half2*)&l.y);
            accy = fmaf(h0.x + l0.x, w4.x, accy);
            accy = fmaf(h0.y + l0.y, w4.y, accy);
            accy = fmaf(h1.x + l1.x, w4.z, accy);
            accy = fmaf(h1.y + l1.y, w4.w, accy);
        }
        yp[((size_t)b * NTILES + tile) * Cc + c] = accy;
    }
}

// ---------------- kernel B: attention = softmax(energy) ----------------
__global__ void softmax_kernel(const float* __restrict__ energy,
                               float* __restrict__ att) {
    __shared__ float red[256];
    int b = blockIdx.x, t = threadIdx.x;
    const float4* e4 = (const float4*)(energy + (size_t)b * Np);
    float4 v[4];
    float m = -INFINITY;
    #pragma unroll
    for (int k = 0; k < 4; ++k) {
        v[k] = e4[k * 256 + t];
        m = fmaxf(m, fmaxf(fmaxf(v[k].x, v[k].y), fmaxf(v[k].z, v[k].w)));
    }
    red[t] = m; __syncthreads();
    for (int off = 128; off; off >>= 1) {
        if (t < off) red[t] = fmaxf(red[t], red[t + off]);
        __syncthreads();
    }
    m = red[0]; __syncthreads();
    float s = 0.f;
    #pragma unroll
    for (int k = 0; k < 4; ++k)
        s += expf(v[k].x - m) + expf(v[k].y - m) + expf(v[k].z - m) + expf(v[k].w - m);
    red[t] = s; __syncthreads();
    for (int off = 128; off; off >>= 1) {
        if (t < off) red[t] += red[t + off];
        __syncthreads();
    }
    float inv = 1.f / red[0];
    float4* a4 = (float4*)(att + (size_t)b * Np);
    #pragma unroll
    for (int k = 0; k < 4; ++k) {
        float4 o;
        o.x = expf(v[k].x - m) * inv;
        o.y = expf(v[k].y - m) * inv;
        o.z = expf(v[k].z - m) * inv;
        o.w = expf(v[k].w - m) * inv;
        a4[k * 256 + t] = o;
    }
}

// ---------------- kernel D1: reduce y partials; d = x_key - (wv @ y + bv) ----------------
__global__ void d_kernel(const float* __restrict__ xk,
                         const float* __restrict__ wv,
                         const float* __restrict__ bv,
                         const float* __restrict__ yp,
                         const float* __restrict__ zp,
                         float* __restrict__ d) {
    __shared__ float ys[Cc];
    int b = blockIdx.y, cq = blockIdx.x, t = threadIdx.x;
    {
        float Z = 0.f;
        #pragma unroll 8
        for (int tt = 0; tt < NTILES; ++tt) Z += zp[b * NTILES + tt];
        float s = 0.f;
        #pragma unroll 8
        for (int tt = 0; tt < NTILES; ++tt)
            s += yp[((size_t)b * NTILES + tt) * Cc + t];
        ys[t] = s / Z;
    }
    __syncthreads();
    int warp = t >> 5, lane = t & 31;
    #pragma unroll
    for (int i = 0; i < 8; ++i) {
        int c = cq * 64 + warp * 8 + i;
        float s = 0.f;
        #pragma unroll
        for (int k = 0; k < 8; ++k) {
            int cp = k * 32 + lane;
            s += wv[(size_t)c * Cc + cp] * ys[cp];
        }
        #pragma unroll
        for (int off = 16; off; off >>= 1) s += __shfl_down_sync(0xFFFFFFFFu, s, off);
        if (lane == 0) d[b * Cc + c] = xk[b * Cc + c] - (s + bv[c]);
    }
}

// ---------------- kernel D2: BN + ReLU + residual ----------------
__global__ void bn_out_kernel(const float* __restrict__ d,
                              const float* __restrict__ wt,
                              const float* __restrict__ bt,
                              const float* __restrict__ gamma,
                              const float* __restrict__ beta,
                              const float* __restrict__ xk,
                              float* __restrict__ out) {
    __shared__ float wts[Cc];
    __shared__ float ts[Bn];
    __shared__ float r1[Bn];
    __shared__ float r2[Bn];
    int c = blockIdx.x, t = threadIdx.x;
    wts[t] = wt[(size_t)c * Cc + t];
    wts[t + 128] = wt[(size_t)c * Cc + t + 128];
    __syncthreads();
    int warp = t >> 5, lane = t & 31;
    for (int i = 0; i < 32; ++i) {
        int b = warp * 32 + i;
        float s = 0.f;
        #pragma unroll
        for (int k = 0; k < 8; ++k) {
            int cp = k * 32 + lane;
            s += wts[cp] * d[b * Cc + cp];
        }
        #pragma unroll
        for (int off = 16; off; off >>= 1) s += __shfl_down_sync(0xFFFFFFFFu, s, off);
        if (lane == 0) ts[b] = s + bt[c];
    }
    __syncthreads();
    float tv = ts[t];
    r1[t] = tv; r2[t] = tv * tv;
    __syncthreads();
    for (int off = 64; off; off >>= 1) {
        if (t < off) { r1[t] += r1[t + off]; r2[t] += r2[t + off]; }
        __syncthreads();
    }
    float mean = r1[0] * (1.f / Bn);
    float var  = r2[0] * (1.f / Bn) - mean * mean;
    float nrm  = (tv - mean) * rsqrtf(var + BN_EPS) * gamma[c] + beta[c];
    out[t * Cc + c] = xk[t * Cc + c] + fmaxf(nrm, 0.f);
}

// ---------------- launch ----------------
extern "C" void kernel_launch(void* const* d_in, const int* in_sizes, int n_in,
                              void* d_out, int out_size) {
    const float* x     = (const float*)d_in[0];
    const float* xkey  = (const float*)d_in[1];
    const float* wq    = (const float*)d_in[2];
    const float* bq    = (const float*)d_in[3];
    const float* wk    = (const float*)d_in[4];
    const float* bk    = (const float*)d_in[5];
    const float* wv    = (const float*)d_in[6];
    const float* bv    = (const float*)d_in[7];
    const float* wt    = (const float*)d_in[8];
    const float* bt    = (const float*)d_in[9];
    const float* gamma = (const float*)d_in[10];
    const float* beta  = (const float*)d_in[11];

    float* out_final = (float*)d_out;
    float* out_att   = (float*)d_out + Bn * Cc;

    float *tk, *energy, *yp, *zp, *dd;
    cudaGetSymbolAddress((void**)&tk,     g_tk);
    cudaGetSymbolAddress((void**)&energy, g_energy);
    cudaGetSymbolAddress((void**)&yp,     g_yp);
    cudaGetSymbolAddress((void**)&zp,     g_zp);
    cudaGetSymbolAddress((void**)&dd,     g_d);

    cudaFuncSetAttribute(fused_kernel, cudaFuncAttributeMaxDynamicSharedMemorySize, ESMEM);

    tk_kernel<<<Bn, 64>>>(xkey, wk, bk, tk);
    fused_kernel<<<dim3(NTILES, Bn), 512, ESMEM>>>(x, wq, bq, tk, energy, yp, zp);
    softmax_kernel<<<Bn, 256>>>(energy, out_att);
    d_kernel<<<dim3(4, Bn), 256>>>(xkey, wv, bv, yp, zp, dd);
    bn_out_kernel<<<Cc, 128>>>(dd, wt, bt, gamma, beta, xkey, out_final);
}

// round 9
// speedup vs baseline: 1.0641x; 1.0641x over previous
#include <cuda_runtime.h>
#include <cuda_fp16.h>
#include <math.h>
#include <stdint.h>

#define Bn   128
#define Cc   256
#define Np   4096
#define CQ   64
#define BN_EPS 1e-5f
#define NT   128                 // n-tile per CTA
#define NTILES (Np / NT)         // 32

// ---------------- scratch (no allocations allowed) ----------------
__device__ float g_tk[Bn * CQ];
__device__ float g_w[Bn * Np];             // unnormalized exp(energy)
__device__ float g_yp[Bn * NTILES * Cc];
__device__ float g_zp[Bn * NTILES];
__device__ float g_d[Bn * Cc];

// ---------------- helpers ----------------
__device__ __forceinline__ uint32_t smem_u32(const void* p) {
    uint32_t a;
    asm("{ .reg .u64 t; cvta.to.shared.u64 t, %1; cvt.u32.u64 %0, t; }" : "=r"(a) : "l"(p));
    return a;
}
__device__ __forceinline__ void ldsm4(uint32_t (&r)[4], uint32_t addr) {
    asm volatile("ldmatrix.sync.aligned.m8n8.x4.shared.b16 {%0,%1,%2,%3}, [%4];"
                 : "=r"(r[0]), "=r"(r[1]), "=r"(r[2]), "=r"(r[3]) : "r"(addr));
}
__device__ __forceinline__ void ldsm4t(uint32_t (&r)[4], uint32_t addr) {
    asm volatile("ldmatrix.sync.aligned.m8n8.x4.trans.shared.b16 {%0,%1,%2,%3}, [%4];"
                 : "=r"(r[0]), "=r"(r[1]), "=r"(r[2]), "=r"(r[3]) : "r"(addr));
}
__device__ __forceinline__ void mma16816(float (&c)[4], const uint32_t (&a)[4],
                                         uint32_t b0, uint32_t b1) {
    asm volatile(
        "mma.sync.aligned.m16n8k16.row.col.f32.f16.f16.f32 "
        "{%0,%1,%2,%3}, {%4,%5,%6,%7}, {%8,%9}, {%0,%1,%2,%3};"
        : "+f"(c[0]), "+f"(c[1]), "+f"(c[2]), "+f"(c[3])
        : "r"(a[0]), "r"(a[1]), "r"(a[2]), "r"(a[3]), "r"(b0), "r"(b1));
}
__device__ __forceinline__ uint32_t h2bits(half2 h) { return *(uint32_t*)&h; }
__device__ __forceinline__ void cvt4h(float4 v, uint32_t& h01, uint32_t& h23) {
    h01 = h2bits(__floats2half2_rn(v.x, v.y));
    h23 = h2bits(__floats2half2_rn(v.z, v.w));
}
__device__ __forceinline__ void split4h(float4 v, uint32_t& h01, uint32_t& h23,
                                        uint32_t& l01, uint32_t& l23) {
    half2 p0 = __floats2half2_rn(v.x, v.y);
    half2 p1 = __floats2half2_rn(v.z, v.w);
    float2 f0 = __half22float2(p0);
    float2 f1 = __half22float2(p1);
    half2 q0 = __floats2half2_rn(v.x - f0.x, v.y - f0.y);
    half2 q1 = __floats2half2_rn(v.z - f1.x, v.w - f1.y);
    h01 = h2bits(p0); h23 = h2bits(p1);
    l01 = h2bits(q0); l23 = h2bits(q1);
}
// fast tanh: (e^{2x}-1)/(e^{2x}+1) with MUFU-based expf/rcp (~1e-6 err)
__device__ __forceinline__ float fast_tanh(float x) {
    float t = __expf(2.f * x);
    return (t - 1.f) * __frcp_rn(t + 1.f);
}

// smem layout (bytes)
#define WSTRB     528            // wq row stride (264 halves)
#define XSTRB     272            // x row stride (136 halves)
#define OFF_WQH   0              // 64*528  = 33792
#define OFF_XH    33792          // 256*272 = 69632
#define OFF_XL    103424         // 69632
#define OFF_E     173056         // 128 floats (w values)
#define OFF_TK    173568         // 64 floats
#define OFF_BQ    173824         // 64 floats
#define OFF_ZR    174080         // 4 floats
#define ESMEM     174144

// ---------------- kernel 0: tk = tanh(wk @ x_key + bk) ----------------
__global__ void tk_kernel(const float* __restrict__ xk,
                          const float* __restrict__ wk,
                          const float* __restrict__ bk,
                          float* __restrict__ tk) {
    __shared__ float xs[Cc];
    int b = blockIdx.x;
    for (int i = threadIdx.x; i < Cc; i += blockDim.x) xs[i] = xk[b * Cc + i];
    __syncthreads();
    int o = threadIdx.x;
    if (o < CQ) {
        float s = bk[o];
        const float* wr = wk + o * Cc;
        #pragma unroll 8
        for (int c = 0; c < Cc; ++c) s += wr[c] * xs[c];
        tk[b * CQ + o] = tanhf(s);
    }
}

// ---------------- fused kernel: energy -> w=exp(e) + y partials ----------------
// grid (32, 128): CTA = (b, 128-n tile). 256 threads = 8 warps x 16 n.
__global__ void __launch_bounds__(256)
fused_kernel(const float* __restrict__ x,
             const float* __restrict__ wq,
             const float* __restrict__ bq,
             const float* __restrict__ tk,
             float* __restrict__ wout,
             float* __restrict__ yp,
             float* __restrict__ zp) {
    extern __shared__ char sm[];
    const uint32_t sb = smem_u32(sm);
    const int tid  = threadIdx.x;
    const int warp = tid >> 5;
    const int lane = tid & 31;
    const int b    = blockIdx.y;
    const int tile = blockIdx.x;
    const int n0   = tile * NT;

    float* tk_s = (float*)(sm + OFF_TK);
    float* bq_s = (float*)(sm + OFF_BQ);
    float* e_s  = (float*)(sm + OFF_E);
    float* zr_s = (float*)(sm + OFF_ZR);

    const float* xg = x + ((size_t)b * Cc) * Np + n0;

    // staging coords: chunk = 64 c x 32 float4 = 2048 float4, 8 per thread
    int sc[8], sj[8];
    #pragma unroll
    for (int f = 0; f < 8; ++f) {
        int idx = f * 256 + tid;
        sc[f] = idx >> 5;          // 0..63
        sj[f] = idx & 31;
    }

    // issue chunk-0 loads FIRST (their latency hides under wq staging)
    float4 pre[8];
    #pragma unroll
    for (int f = 0; f < 8; ++f)
        pre[f] = *(const float4*)(xg + (size_t)sc[f] * Np + 4 * sj[f]);

    // ---- stage wq (fp16 hi only) ----
    {
        const float4* wq4 = (const float4*)wq;
        #pragma unroll
        for (int f = 0; f < 16; ++f) {
            int idx = f * 256 + tid;       // 4096 float4 = 64 o x 64 j (c=4j)
            int o = idx >> 6;
            int j = idx & 63;
            float4 v = wq4[idx];
            uint32_t h01, h23;
            cvt4h(v, h01, h23);
            *(uint2*)(sm + OFF_WQH + (uint32_t)o * WSTRB + j * 8) = make_uint2(h01, h23);
        }
    }
    if (tid < CQ) {
        tk_s[tid] = tk[b * CQ + tid];
        bq_s[tid] = bq[tid];
    }

    // accumulators: 4 m-tiles (o) x 2 n-tiles x 4
    float acc[4][2][4];
    #pragma unroll
    for (int mt = 0; mt < 4; ++mt)
        #pragma unroll
        for (int nt = 0; nt < 2; ++nt)
            #pragma unroll
            for (int e = 0; e < 4; ++e) acc[mt][nt][e] = 0.f;

    const uint32_t a_off = (uint32_t)(lane & 15) * WSTRB + (uint32_t)(lane >> 4) * 16;
    const uint32_t b_off = (uint32_t)(((lane >> 3) & 1) * 8 + (lane & 7)) * XSTRB
                         + (uint32_t)(lane >> 4) * 16 + (uint32_t)warp * 32;

    for (int ch = 0; ch < 4; ++ch) {
        // convert + store chunk ch (hi/lo split of x)
        #pragma unroll
        for (int f = 0; f < 8; ++f) {
            uint32_t h01, h23, l01, l23;
            split4h(pre[f], h01, h23, l01, l23);
            uint32_t off = (uint32_t)(ch * 64 + sc[f]) * XSTRB + sj[f] * 8;
            *(uint2*)(sm + OFF_XH + off) = make_uint2(h01, h23);
            *(uint2*)(sm + OFF_XL + off) = make_uint2(l01, l23);
        }
        __syncthreads();

        // prefetch next chunk (hides under the 64 MMAs below)
        if (ch < 3) {
            #pragma unroll
            for (int f = 0; f < 8; ++f)
                pre[f] = *(const float4*)(xg + (size_t)((ch + 1) * 64 + sc[f]) * Np + 4 * sj[f]);
        }

        #pragma unroll
        for (int kk = 0; kk < 4; ++kk) {
            uint32_t c_b  = (uint32_t)(ch * 64 + kk * 16) * 2;
            uint32_t krow = (uint32_t)(ch * 64 + kk * 16) * XSTRB;

            uint32_t a_h[4][4];
            #pragma unroll
            for (int mt = 0; mt < 4; ++mt)
                ldsm4(a_h[mt], sb + OFF_WQH + (uint32_t)mt * (16 * WSTRB) + c_b + a_off);
            uint32_t b_hi[4], b_lo[4];
            ldsm4t(b_hi, sb + OFF_XH + krow + b_off);
            ldsm4t(b_lo, sb + OFF_XL + krow + b_off);

            #pragma unroll
            for (int mt = 0; mt < 4; ++mt)
                #pragma unroll
                for (int nt = 0; nt < 2; ++nt) {
                    int hb = nt * 2;
                    mma16816(acc[mt][nt], a_h[mt], b_hi[hb], b_hi[hb + 1]);
                    mma16816(acc[mt][nt], a_h[mt], b_lo[hb], b_lo[hb + 1]);
                }
        }
    }

    // ---- epilogue: fast tanh, dot with tk, reduce over o, w = exp(e) ----
    {
        const int r = lane >> 2;
        float s0[2] = {0.f, 0.f};
        float s1[2] = {0.f, 0.f};
        #pragma unroll
        for (int mt = 0; mt < 4; ++mt) {
            float bq1 = bq_s[mt * 16 + r],     tk1 = tk_s[mt * 16 + r];
            float bq2 = bq_s[mt * 16 + r + 8], tk2 = tk_s[mt * 16 + r + 8];
            #pragma unroll
            for (int nt = 0; nt < 2; ++nt) {
                s0[nt] += fast_tanh(acc[mt][nt][0] + bq1) * tk1
                        + fast_tanh(acc[mt][nt][2] + bq2) * tk2;
                s1[nt] += fast_tanh(acc[mt][nt][1] + bq1) * tk1
                        + fast_tanh(acc[mt][nt][3] + bq2) * tk2;
            }
        }
        #pragma unroll
        for (int nt = 0; nt < 2; ++nt) {
            #pragma unroll
            for (int d = 4; d < 32; d <<= 1) {
                s0[nt] += __shfl_xor_sync(0xFFFFFFFFu, s0[nt], d);
                s1[nt] += __shfl_xor_sync(0xFFFFFFFFu, s1[nt], d);
            }
        }
        if (lane < 4) {
            #pragma unroll
            for (int nt = 0; nt < 2; ++nt) {
                int nl = warp * 16 + nt * 8 + 2 * lane;
                // |e| < 64 always -> exp never overflows; softmax == w / sum(w)
                float2 wv = make_float2(__expf(s0[nt]), __expf(s1[nt]));
                *(float2*)(e_s + nl) = wv;
                *(float2*)(wout + (size_t)b * Np + n0 + nl) = wv;
            }
        }
    }
    __syncthreads();

    // ---- Z partial ----
    if (tid < NT) {
        float s = e_s[tid];
        #pragma unroll
        for (int d = 16; d; d >>= 1) s += __shfl_xor_sync(0xFFFFFFFFu, s, d);
        if (lane == 0) zr_s[tid >> 5] = s;
    }
    __syncthreads();
    if (tid == 0) zp[b * NTILES + tile] = zr_s[0] + zr_s[1] + zr_s[2] + zr_s[3];

    // ---- y partial: y_p[c] = sum_n x[c,n] * w[n] ----
    {
        int c = tid;
        const uint2* hrow = (const uint2*)(sm + OFF_XH + (uint32_t)c * XSTRB);
        const uint2* lrow = (const uint2*)(sm + OFF_XL + (uint32_t)c * XSTRB);
        float accy = 0.f;
        #pragma unroll 8
        for (int j = 0; j < 32; ++j) {
            uint2 h = hrow[j];
            uint2 l = lrow[j];
            float4 w4 = *(const float4*)(e_s + 4 * j);
            float2 h0 = __half22float2(*(half2*)&h.x);
            float2 h1 = __half22float2(*(half2*)&h.y);
            float2 l0 = __half22float2(*(half2*)&l.x);
            float2 l1 = __half22float2(*(half2*)&l.y);
            accy = fmaf(h0.x + l0.x, w4.x, accy);
            accy = fmaf(h0.y + l0.y, w4.y, accy);
            accy = fmaf(h1.x + l1.x, w4.z, accy);
            accy = fmaf(h1.y + l1.y, w4.w, accy);
        }
        yp[((size_t)b * NTILES + tile) * Cc + c] = accy;
    }
}

// ---------------- kernel B: att = w / Z (streaming scale) ----------------
__global__ void scale_kernel(const float* __restrict__ w,
                             const float* __restrict__ zp,
                             float* __restrict__ att) {
    __shared__ float invZ;
    int b = blockIdx.x, t = threadIdx.x;   // 512 threads
    if (t < 32) {
        float z = zp[b * NTILES + t];
        #pragma unroll
        for (int d = 16; d; d >>= 1) z += __shfl_xor_sync(0xFFFFFFFFu, z, d);
        if (t == 0) invZ = 1.f / z;
    }
    __syncthreads();
    float iz = invZ;
    const float4* w4 = (const float4*)(w + (size_t)b * Np);
    float4* a4 = (float4*)(att + (size_t)b * Np);
    #pragma unroll
    for (int k = 0; k < 2; ++k) {
        int idx = k * 512 + t;
        float4 v = w4[idx];
        v.x *= iz; v.y *= iz; v.z *= iz; v.w *= iz;
        a4[idx] = v;
    }
}

// ---------------- kernel D1: reduce y partials; d = x_key - (wv @ y + bv) ----------------
// grid (8, Bn): block computes 32 outputs c; y/Z reduce duplicated per block.
__global__ void d_kernel(const float* __restrict__ xk,
                         const float* __restrict__ wv,
                         const float* __restrict__ bv,
                         const float* __restrict__ yp,
                         const float* __restrict__ zp,
                         float* __restrict__ d) {
    __shared__ float ys[Cc];
    int b = blockIdx.y, cq = blockIdx.x, t = threadIdx.x;
    {
        float Z = 0.f;
        #pragma unroll 8
        for (int tt = 0; tt < NTILES; ++tt) Z += zp[b * NTILES + tt];
        float s = 0.f;
        #pragma unroll 8
        for (int tt = 0; tt < NTILES; ++tt)
            s += yp[((size_t)b * NTILES + tt) * Cc + t];
        ys[t] = s / Z;
    }
    __syncthreads();
    int warp = t >> 5, lane = t & 31;
    #pragma unroll
    for (int i = 0; i < 4; ++i) {
        int c = cq * 32 + warp * 4 + i;
        float s = 0.f;
        #pragma unroll
        for (int k = 0; k < 8; ++k) {
            int cp = k * 32 + lane;
            s += wv[(size_t)c * Cc + cp] * ys[cp];
        }
        #pragma unroll
        for (int off = 16; off; off >>= 1) s += __shfl_down_sync(0xFFFFFFFFu, s, off);
        if (lane == 0) d[b * Cc + c] = xk[b * Cc + c] - (s + bv[c]);
    }
}

// ---------------- kernel D2: BN + ReLU + residual ----------------
__global__ void bn_out_kernel(const float* __restrict__ d,
                              const float* __restrict__ wt,
                              const float* __restrict__ bt,
                              const float* __restrict__ gamma,
                              const float* __restrict__ beta,
                              const float* __restrict__ xk,
                              float* __restrict__ out) {
    __shared__ float wts[Cc];
    __shared__ float ts[Bn];
    __shared__ float r1[Bn];
    __shared__ float r2[Bn];
    int c = blockIdx.x, t = threadIdx.x;
    wts[t] = wt[(size_t)c * Cc + t];
    wts[t + 128] = wt[(size_t)c * Cc + t + 128];
    __syncthreads();
    int warp = t >> 5, lane = t & 31;
    for (int i = 0; i < 32; ++i) {
        int b = warp * 32 + i;
        float s = 0.f;
        #pragma unroll
        for (int k = 0; k < 8; ++k) {
            int cp = k * 32 + lane;
            s += wts[cp] * d[b * Cc + cp];
        }
        #pragma unroll
        for (int off = 16; off; off >>= 1) s += __shfl_down_sync(0xFFFFFFFFu, s, off);
        if (lane == 0) ts[b] = s + bt[c];
    }
    __syncthreads();
    float tv = ts[t];
    r1[t] = tv; r2[t] = tv * tv;
    __syncthreads();
    for (int off = 64; off; off >>= 1) {
        if (t < off) { r1[t] += r1[t + off]; r2[t] += r2[t + off]; }
        __syncthreads();
    }
    float mean = r1[0] * (1.f / Bn);
    float var  = r2[0] * (1.f / Bn) - mean * mean;
    float nrm  = (tv - mean) * rsqrtf(var + BN_EPS) * gamma[c] + beta[c];
    out[t * Cc + c] = xk[t * Cc + c] + fmaxf(nrm, 0.f);
}

// ---------------- launch ----------------
extern "C" void kernel_launch(void* const* d_in, const int* in_sizes, int n_in,
                              void* d_out, int out_size) {
    const float* x     = (const float*)d_in[0];
    const float* xkey  = (const float*)d_in[1];
    const float* wq    = (const float*)d_in[2];
    const float* bq    = (const float*)d_in[3];
    const float* wk    = (const float*)d_in[4];
    const float* bk    = (const float*)d_in[5];
    const float* wv    = (const float*)d_in[6];
    const float* bv    = (const float*)d_in[7];
    const float* wt    = (const float*)d_in[8];
    const float* bt    = (const float*)d_in[9];
    const float* gamma = (const float*)d_in[10];
    const float* beta  = (const float*)d_in[11];

    float* out_final = (float*)d_out;
    float* out_att   = (float*)d_out + Bn * Cc;

    float *tk, *wbuf, *yp, *zp, *dd;
    cudaGetSymbolAddress((void**)&tk,   g_tk);
    cudaGetSymbolAddress((void**)&wbuf, g_w);
    cudaGetSymbolAddress((void**)&yp,   g_yp);
    cudaGetSymbolAddress((void**)&zp,   g_zp);
    cudaGetSymbolAddress((void**)&dd,   g_d);

    cudaFuncSetAttribute(fused_kernel, cudaFuncAttributeMaxDynamicSharedMemorySize, ESMEM);

    tk_kernel<<<Bn, 64>>>(xkey, wk, bk, tk);
    fused_kernel<<<dim3(NTILES, Bn), 256, ESMEM>>>(x, wq, bq, tk, wbuf, yp, zp);
    scale_kernel<<<Bn, 512>>>(wbuf, zp, out_att);
    d_kernel<<<dim3(8, Bn), 256>>>(xkey, wv, bv, yp, zp, dd);
    bn_out_kernel<<<Cc, 128>>>(dd, wt, bt, gamma, beta, xkey, out_final);
}